// round 17
// baseline (speedup 1.0000x reference)
#include <cuda_runtime.h>
#include <cuda_bf16.h>
#include <cstdint>

// ---------------------------------------------------------------------------
// BVP Helmholtz residual via 2nd-order jet propagation on mma.sync bf16 HMMA
// (3-pass hi/lo split). Round 17: TWO independent 16-sample tiles (M=80,
// zero pad waste) in one 512-thread CTA. Each tile: 8 warps, warp = mt5 x nt4
// (60 MMAs/chunk) with a PRIVATE single-stage B slice + in-register double
// buffering (ldsm B frags, then reissue same buffer with next chunk).
// ZERO mainloop barriers; tiles share no sync until the final output, so one
// tile's epilogue phases overlap the other tile's MMA mainloop.
// ---------------------------------------------------------------------------

#define HD 256
#define SB 32              // samples per CTA = 2 tiles x 16
#define AROW 1040          // A row bytes: hi[0,512) pad lo[528,1040) == D row
#define DROW 260           // D row stride in floats (= 1040 B)
#define BROW 80            // B slice row: hi k16 (32B) + lo k16 (32B) + pad
#define BSTG 2560          // 32 rows * 80 = one warp's single-stage slice
#define ATILE 83200        // 80*1040

#define A_OFF 0            // 2 tiles * 83200 = 166400
#define B_OFF 166400       // 2 tiles * 8 slices * 2560 = 40960
#define XYZF_OFF 207360    // 512
#define PART_OFF 207872    // 2 tiles * 2048 = 4096
#define SMEM_BYTES 211968

// prepped weights: [layer][split hi/lo][n][k] bf16
__device__ __align__(16) __nv_bfloat16 Wbf[2][2][HD][HD];

__global__ __launch_bounds__(256)
void prep_weights(const float* __restrict__ W2, const float* __restrict__ W3)
{
    int t = blockIdx.x * 256 + threadIdx.x;      // 131072
    int layer = t >> 16, n = (t >> 8) & 255, k = t & 255;
    float w = (layer ? W3 : W2)[n * HD + k];
    __nv_bfloat16 h = __float2bfloat16(w);
    __nv_bfloat16 l = __float2bfloat16(w - __bfloat162float(h));
    Wbf[layer][0][n][k] = h;
    Wbf[layer][1][n][k] = l;
}

__device__ __forceinline__ uint32_t smem_u32(const void* p) {
    uint32_t a;
    asm("{ .reg .u64 t; cvta.to.shared.u64 t, %1; cvt.u32.u64 %0, t; }"
        : "=r"(a) : "l"(p));
    return a;
}
__device__ __forceinline__ void ldsm4(uint32_t* r, uint32_t a) {
    asm volatile("ldmatrix.sync.aligned.m8n8.x4.shared.b16 {%0,%1,%2,%3}, [%4];"
                 : "=r"(r[0]), "=r"(r[1]), "=r"(r[2]), "=r"(r[3]) : "r"(a));
}
__device__ __forceinline__ void mma_bf16(float* c, const uint32_t* a,
                                         const uint32_t* b) {
    asm volatile("mma.sync.aligned.m16n8k16.row.col.f32.bf16.bf16.f32 "
                 "{%0,%1,%2,%3}, {%4,%5,%6,%7}, {%8,%9}, {%0,%1,%2,%3};"
                 : "+f"(c[0]), "+f"(c[1]), "+f"(c[2]), "+f"(c[3])
                 : "r"(a[0]), "r"(a[1]), "r"(a[2]), "r"(a[3]),
                   "r"(b[0]), "r"(b[1]));
}
__device__ __forceinline__ void cp16(uint32_t sa, const void* ga) {
    asm volatile("cp.async.cg.shared.global [%0], [%1], 16;"
                 :: "r"(sa), "l"(__cvta_generic_to_global(ga)) : "memory");
}
#define CP_COMMIT() asm volatile("cp.async.commit_group;" ::: "memory")
#define CP_WAIT0()  asm volatile("cp.async.wait_group 0;" ::: "memory")
// per-tile named barrier (256 threads, contiguous tids); ids 1,2
#define TBAR(t) asm volatile("bar.sync %0, 256;" :: "r"((t) + 1) : "memory")

// fast tanh: 1 - 2/(exp(2u)+1). abs err ~3e-7.
__device__ __forceinline__ float ftanh(float u) {
    float e = __expf(2.0f * u);
    return 1.0f - __fdividef(2.0f, e + 1.0f);
}

__global__ __launch_bounds__(512, 1)
void bvp_mma_kernel(const float* __restrict__ gx, const float* __restrict__ gy,
                    const float* __restrict__ gz, const float* __restrict__ gf,
                    const float* __restrict__ W1, const float* __restrict__ b1,
                    const float* __restrict__ b2, const float* __restrict__ b3,
                    const float* __restrict__ W4, const float* __restrict__ b4,
                    float* __restrict__ out, int N)
{
    extern __shared__ char sm[];
    const uint32_t smb = smem_u32(sm);
    float* xyzf = (float*)(sm + XYZF_OFF);

    const int tid  = threadIdx.x;
    const int wid  = tid >> 5;
    const int lid  = tid & 31;
    const int tile = wid >> 3;                // tile 0/1 (tids contiguous)
    const int ng   = wid & 7;                 // n-slice (cols ng*32..+32)
    const int n0w  = ng << 5;
    const int n0   = blockIdx.x * SB;
    const int ttid = tid & 255;               // thread id within tile
    const int cp   = ttid & 127;              // column pair
    const int half = ttid >> 7;               // 8 samples each

    char* At = sm + A_OFF + tile * ATILE;     // tile's A (aliased by D)
    float* Dst = (float*)At;
    float* part = (float*)(sm + PART_OFF + tile * 2048);  // [16][8][4]

    const float CX = (float)((0.5 * 0.6) * (0.5 * 0.6));
    const float CY = (float)((0.7 * 0.6) * (0.7 * 0.6));
    const float CZ = (float)((0.7 * 0.5) * (0.7 * 0.5));

    // warp-private single-stage B slice
    const uint32_t myb = smb + B_OFF + tile * 20480 + ng * BSTG;
    auto issue_chunk = [&](int gi) {          // gi in [0,32): layer*16 + kc
        int L = gi >> 4, kc = gi & 15;
        #pragma unroll
        for (int j = 0; j < 4; ++j) {
            int idx = lid + (j << 5);         // 0..127
            int r = idx >> 2, q = idx & 3;
            int split = q >> 1, hf = q & 1;
            cp16(myb + r * BROW + split * 32 + hf * 16,
                 &Wbf[L][split][n0w + r][kc * 16 + hf * 8]);
        }
        CP_COMMIT();
    };

    // packed store of a column pair (hi word + lo word) into tile A
    auto storeA2 = [&](int m, float v0, float v1) {
        __nv_bfloat16 h0 = __float2bfloat16(v0);
        __nv_bfloat16 h1 = __float2bfloat16(v1);
        __nv_bfloat16 l0 = __float2bfloat16(v0 - __bfloat162float(h0));
        __nv_bfloat16 l1 = __float2bfloat16(v1 - __bfloat162float(h1));
        uint32_t wh = (uint32_t)__bfloat16_as_ushort(h0) |
                      ((uint32_t)__bfloat16_as_ushort(h1) << 16);
        uint32_t wl = (uint32_t)__bfloat16_as_ushort(l0) |
                      ((uint32_t)__bfloat16_as_ushort(l1) << 16);
        char* base = At + m * AROW + cp * 4;
        *(uint32_t*)(base)       = wh;
        *(uint32_t*)(base + 528) = wl;
    };

    // prologue: each warp prefetches chunk 0 of its private slice
    issue_chunk(0);

    // coords (full CTA, single full sync at start)
    if (tid < 128) {
        int ss = tid >> 2, w = tid & 3;
        int n = n0 + ss; if (n >= N) n = N - 1;
        const float* p = (w == 0) ? gx : (w == 1) ? gy : (w == 2) ? gz : gf;
        xyzf[tid] = p[n];
    }
    __syncthreads();

    // ---- layer 1: 4 -> 256, jets analytically (per tile, packed) -----------
    {
        float4 w0 = *(const float4*)(W1 + (cp * 2) * 4);
        float4 w1 = *(const float4*)(W1 + (cp * 2 + 1) * 4);
        float2 bv = *(const float2*)(b1 + cp * 2);
        float g0 = CX * w0.x * w0.x + CY * w0.y * w0.y + CZ * w0.z * w0.z;
        float g1 = CX * w1.x * w1.x + CY * w1.y * w1.y + CZ * w1.z * w1.z;
        #pragma unroll 1
        for (int s8 = 0; s8 < 8; ++s8) {
            int sl = half * 8 + s8;           // local sample 0..15
            int sg = tile * 16 + sl;          // xyzf index
            float xs = xyzf[sg * 4 + 0], ys = xyzf[sg * 4 + 1];
            float zs = xyzf[sg * 4 + 2], fs = xyzf[sg * 4 + 3];
            float u0 = fmaf(w0.x, xs, fmaf(w0.y, ys, fmaf(w0.z, zs,
                       fmaf(w0.w, fs, bv.x))));
            float u1 = fmaf(w1.x, xs, fmaf(w1.y, ys, fmaf(w1.z, zs,
                       fmaf(w1.w, fs, bv.y))));
            float y0 = ftanh(u0), y1 = ftanh(u1);
            float s0 = fmaf(-y0, y0, 1.0f), s1 = fmaf(-y1, y1, 1.0f);
            int m = sl * 5;
            storeA2(m + 0, y0, y1);
            storeA2(m + 1, s0 * w0.x, s1 * w1.x);
            storeA2(m + 2, s0 * w0.y, s1 * w1.y);
            storeA2(m + 3, s0 * w0.z, s1 * w1.z);
            storeA2(m + 4, -2.0f * y0 * s0 * g0, -2.0f * y1 * s1 * g1);
        }
    }
    TBAR(tile);

    const int g = lid >> 2, cc = (lid & 3) << 1;

    // ---- hidden layers 2,3 (barrier-free mainloop) ---------------------------
    #pragma unroll 1
    for (int L = 0; L < 2; ++L) {
        float acc[5][4][4];
        #pragma unroll
        for (int mt = 0; mt < 5; ++mt)
            #pragma unroll
            for (int nt = 0; nt < 4; ++nt)
                #pragma unroll
                for (int r = 0; r < 4; ++r) acc[mt][nt][r] = 0.f;

        #pragma unroll 1
        for (int kc = 0; kc < 16; ++kc) {     // k16 chunks
            int gi = (L << 4) | kc;
            CP_WAIT0();                       // this warp's chunk gi landed
            // capture B fragments into registers (one ldsm4: hi regs 0,1 /
            // lo regs 2,3 via lane-16+ offset)
            uint32_t bf[4][4];
            #pragma unroll
            for (int nt = 0; nt < 4; ++nt) {
                uint32_t ba = myb + ((nt << 3) + (lid & 7)) * BROW +
                              (lid & 8) * 2 + ((lid >> 4) << 5);
                ldsm4(bf[nt], ba);
            }
            // refill the SAME buffer with next chunk (regs already captured;
            // cp.async smem write trails its global read by >= L2 latency)
            if (gi + 1 < 32) issue_chunk(gi + 1);

            #pragma unroll
            for (int mt = 0; mt < 5; ++mt) {
                uint32_t aa = smb + (uint32_t)(At - sm) +
                              ((mt << 4) + (lid & 15)) * AROW +
                              (kc * 16 + ((lid >> 4) << 3)) * 2;
                uint32_t ah[4], al[4];
                ldsm4(ah, aa);
                ldsm4(al, aa + 528);
                #pragma unroll
                for (int nt = 0; nt < 4; ++nt) {
                    mma_bf16(acc[mt][nt], ah, &bf[nt][0]);  // hi*hi
                    mma_bf16(acc[mt][nt], al, &bf[nt][0]);  // lo*hi
                    mma_bf16(acc[mt][nt], ah, &bf[nt][2]);  // hi*lo
                }
            }
        }
        TBAR(tile);   // all tile MMA reads of A done before D overwrites A

        // ---- stage acc into D (aliases dead A rows of this tile) ------------
        #pragma unroll
        for (int mt = 0; mt < 5; ++mt)
            #pragma unroll
            for (int nt = 0; nt < 4; ++nt) {
                int m0 = (mt << 4), nc = n0w + (nt << 3) + cc;
                *(float2*)(Dst + (m0 + g) * DROW + nc) =
                    make_float2(acc[mt][nt][0], acc[mt][nt][1]);
                *(float2*)(Dst + (m0 + g + 8) * DROW + nc) =
                    make_float2(acc[mt][nt][2], acc[mt][nt][3]);
            }
        TBAR(tile);

        // ---- activation epilogue (per tile) ----------------------------------
        if (L == 0) {
            float2 bn2 = *(const float2*)(b2 + cp * 2);
            #pragma unroll 1
            for (int bb = 0; bb < 4; ++bb) {
                float2 t5[2][5];
                #pragma unroll
                for (int j = 0; j < 2; ++j) {
                    int mr = (half * 8 + bb * 2 + j) * 5;
                    #pragma unroll
                    for (int ch = 0; ch < 5; ++ch)
                        t5[j][ch] = *(float2*)(Dst + (mr + ch) * DROW + cp * 2);
                }
                TBAR(tile);                // all reads of these rows done
                #pragma unroll
                for (int j = 0; j < 2; ++j) {
                    int mr = (half * 8 + bb * 2 + j) * 5;
                    float y0 = ftanh(t5[j][0].x + bn2.x);
                    float y1 = ftanh(t5[j][0].y + bn2.y);
                    float s0 = fmaf(-y0, y0, 1.0f);
                    float s1 = fmaf(-y1, y1, 1.0f);
                    float g0 = CX * t5[j][1].x * t5[j][1].x +
                               CY * t5[j][2].x * t5[j][2].x +
                               CZ * t5[j][3].x * t5[j][3].x;
                    float g1 = CX * t5[j][1].y * t5[j][1].y +
                               CY * t5[j][2].y * t5[j][2].y +
                               CZ * t5[j][3].y * t5[j][3].y;
                    storeA2(mr + 0, y0, y1);
                    storeA2(mr + 1, s0 * t5[j][1].x, s1 * t5[j][1].y);
                    storeA2(mr + 2, s0 * t5[j][2].x, s1 * t5[j][2].y);
                    storeA2(mr + 3, s0 * t5[j][3].x, s1 * t5[j][3].y);
                    storeA2(mr + 4,
                            fmaf(s0, t5[j][4].x, -2.0f * y0 * s0 * g0),
                            fmaf(s1, t5[j][4].y, -2.0f * y1 * s1 * g1));
                }
            }
            TBAR(tile);
        } else {
            const int col = ttid;
            float bn  = b3[col];
            float w40 = W4[col], w41 = W4[HD + col];
            #pragma unroll 1
            for (int sl = 0; sl < 16; ++sl) {
                int mr = sl * 5;
                float u  = Dst[(mr + 0) * DROW + col] + bn;
                float tx = Dst[(mr + 1) * DROW + col];
                float ty = Dst[(mr + 2) * DROW + col];
                float tz = Dst[(mr + 3) * DROW + col];
                float qa = Dst[(mr + 4) * DROW + col];
                float yv = ftanh(u);
                float sgm = fmaf(-yv, yv, 1.0f);
                float gq = CX * tx * tx + CY * ty * ty + CZ * tz * tz;
                float qn = fmaf(sgm, qa, -2.0f * yv * sgm * gq);
                float v0 = w40 * yv, v1 = w41 * yv;
                float v2 = w40 * qn, v3 = w41 * qn;
                #pragma unroll
                for (int o = 16; o; o >>= 1) {
                    v0 += __shfl_xor_sync(0xFFFFFFFFu, v0, o);
                    v1 += __shfl_xor_sync(0xFFFFFFFFu, v1, o);
                    v2 += __shfl_xor_sync(0xFFFFFFFFu, v2, o);
                    v3 += __shfl_xor_sync(0xFFFFFFFFu, v3, o);
                }
                if (lid == 0) {
                    float* pp = part + (sl * 8 + ng) * 4;
                    pp[0] = v0; pp[1] = v1; pp[2] = v2; pp[3] = v3;
                }
            }
        }
    }

    // ---- residual output (needs both tiles' part) -----------------------------
    __syncthreads();
    if (tid < SB) {
        int n = n0 + tid;
        if (n < N) {
            const float* pbase = (float*)(sm + PART_OFF + (tid >> 4) * 2048);
            int sl = tid & 15;
            float P0 = 0.f, P1 = 0.f, Q0 = 0.f, Q1 = 0.f;
            #pragma unroll
            for (int w = 0; w < 8; ++w) {
                const float* pp = pbase + (sl * 8 + w) * 4;
                P0 += pp[0]; P1 += pp[1]; Q0 += pp[2]; Q1 += pp[3];
            }
            P0 += b4[0]; P1 += b4[1];
            float fs = xyzf[tid * 4 + 3];
            float kw = 6.283185307179586f * fmaf(fs, 500.0f, 100.0f) / 343.0f;
            float kx = 0.21f * kw;
            float K2 = kx * kx;
            out[n]     = 2.0f * Q0 + K2 * fmaf(2.0f, P0, 0.1f);
            out[N + n] = 1.5f * Q1 + K2 * fmaf(1.5f, P1, -0.05f);
        }
    }
}

extern "C" void kernel_launch(void* const* d_in, const int* in_sizes, int n_in,
                              void* d_out, int out_size)
{
    const float* x  = (const float*)d_in[0];
    const float* y  = (const float*)d_in[1];
    const float* z  = (const float*)d_in[2];
    const float* f  = (const float*)d_in[3];
    const float* W1 = (const float*)d_in[4];
    const float* b1 = (const float*)d_in[5];
    const float* W2 = (const float*)d_in[6];
    const float* b2 = (const float*)d_in[7];
    const float* W3 = (const float*)d_in[8];
    const float* b3 = (const float*)d_in[9];
    const float* W4 = (const float*)d_in[10];
    const float* b4 = (const float*)d_in[11];
    float* out = (float*)d_out;

    int N = in_sizes[0];
    prep_weights<<<512, 256>>>(W2, W3);

    cudaFuncSetAttribute(bvp_mma_kernel,
                         cudaFuncAttributeMaxDynamicSharedMemorySize,
                         SMEM_BYTES);
    int blocks = (N + SB - 1) / SB;
    bvp_mma_kernel<<<blocks, 512, SMEM_BYTES>>>(x, y, z, f, W1, b1, b2, b3,
                                                W4, b4, out, N);
}